// round 1
// baseline (speedup 1.0000x reference)
#include <cuda_runtime.h>
#include <cuda_bf16.h>
#include <cstdint>
#include <math_constants.h>

// Problem constants (fixed by setup_inputs)
#define BATCH 2
#define LV 1920
#define LT 128
#define LSEQ 2048            // LV + LT per batch
#define NTOK 4096            // BATCH * LSEQ
#define NH 12
#define HD 128
#define DIMIN 1536
#define QKVN 4608            // 3 * NH * HD
#define EPSV 1e-6f

// ---------------- scratch (device globals; no allocation allowed) ----------------
__device__ float g_qkv[(size_t)NTOK * QKVN];                    // 75.5 MB
__device__ __nv_bfloat16 g_q[(size_t)BATCH * NH * LSEQ * HD];   // 12.6 MB
__device__ __nv_bfloat16 g_k[(size_t)BATCH * NH * LSEQ * HD];
__device__ __nv_bfloat16 g_v[(size_t)BATCH * NH * LSEQ * HD];
__device__ float g_attn[(size_t)NTOK * (NH * HD)];              // 25.2 MB

// =====================================================================
// Kernel 1: QKV projection  out[t, 0:4608] = x[t] @ Wqkv_stream + b
// 64x64 tile, BK=16, 256 threads, 4x4 per thread, fp32 FFMA
// =====================================================================
__global__ void __launch_bounds__(256) gemm_qkv_kernel(
    const float* __restrict__ vid, const float* __restrict__ txt,
    const float* __restrict__ Wv, const float* __restrict__ bv,
    const float* __restrict__ Wt, const float* __restrict__ bt)
{
    __shared__ __align__(16) float As[16][64];
    __shared__ __align__(16) float Bs[16][64];

    const int row0 = blockIdx.y * 64;
    const int col0 = blockIdx.x * 64;
    const int b = row0 >> 11;          // 2048 rows per batch
    const int l0 = row0 & 2047;

    const float* X; const float* W; const float* bias;
    if (l0 < LV) { X = vid + (size_t)(b * LV + l0) * DIMIN;       W = Wv; bias = bv; }
    else         { X = txt + (size_t)(b * LT + (l0 - LV)) * DIMIN; W = Wt; bias = bt; }

    const int tid = threadIdx.x;
    const int tr = tid >> 4, tc = tid & 15;
    const int arow = tid >> 2,  ac4 = (tid & 3) << 2;
    const int brow = tid >> 4,  bc4 = (tid & 15) << 2;

    float acc[4][4] = {};

    for (int k0 = 0; k0 < DIMIN; k0 += 16) {
        float4 a = *reinterpret_cast<const float4*>(X + (size_t)arow * DIMIN + k0 + ac4);
        As[ac4 + 0][arow] = a.x; As[ac4 + 1][arow] = a.y;
        As[ac4 + 2][arow] = a.z; As[ac4 + 3][arow] = a.w;
        *reinterpret_cast<float4*>(&Bs[brow][bc4]) =
            *reinterpret_cast<const float4*>(W + (size_t)(k0 + brow) * QKVN + col0 + bc4);
        __syncthreads();
        #pragma unroll
        for (int k = 0; k < 16; k++) {
            float4 av = *reinterpret_cast<const float4*>(&As[k][tr << 2]);
            float4 bw = *reinterpret_cast<const float4*>(&Bs[k][tc << 2]);
            float ar[4] = {av.x, av.y, av.z, av.w};
            float br[4] = {bw.x, bw.y, bw.z, bw.w};
            #pragma unroll
            for (int i = 0; i < 4; i++)
                #pragma unroll
                for (int j = 0; j < 4; j++)
                    acc[i][j] = fmaf(ar[i], br[j], acc[i][j]);
        }
        __syncthreads();
    }

    #pragma unroll
    for (int i = 0; i < 4; i++) {
        int r = row0 + (tr << 2) + i;
        int c = col0 + (tc << 2);
        float4 bb = *reinterpret_cast<const float4*>(&bias[c]);
        float4 o = make_float4(acc[i][0] + bb.x, acc[i][1] + bb.y,
                               acc[i][2] + bb.z, acc[i][3] + bb.w);
        *reinterpret_cast<float4*>(&g_qkv[(size_t)r * QKVN + c]) = o;
    }
}

// =====================================================================
// Kernel 2: per-(token, head) RMSNorm on q, k; cast q,k,v -> bf16
// packed head-major: [b][h][l][d]
// grid (NH, NTOK), 128 threads (one per d)
// =====================================================================
__global__ void __launch_bounds__(128) norm_pack_kernel(
    const float* __restrict__ nq_vid, const float* __restrict__ nk_vid,
    const float* __restrict__ nq_txt, const float* __restrict__ nk_txt)
{
    const int h = blockIdx.x;
    const int t = blockIdx.y;
    const int d = threadIdx.x;
    const int b = t >> 11, l = t & 2047;
    const bool is_vid = (l < LV);

    const float* base = g_qkv + (size_t)t * QKVN + h * HD;
    float xq = base[d];
    float xk = base[DIMIN + d];
    float xv = base[2 * DIMIN + d];

    float sq = xq * xq, sk = xk * xk;
    #pragma unroll
    for (int o = 16; o; o >>= 1) {
        sq += __shfl_down_sync(0xffffffffu, sq, o);
        sk += __shfl_down_sync(0xffffffffu, sk, o);
    }
    __shared__ float shq[4], shk[4];
    const int wid = d >> 5, lane = d & 31;
    if (lane == 0) { shq[wid] = sq; shk[wid] = sk; }
    __syncthreads();
    float tq = shq[0] + shq[1] + shq[2] + shq[3];
    float tk = shk[0] + shk[1] + shk[2] + shk[3];
    float rq = rsqrtf(tq * (1.0f / HD) + EPSV);
    float rk = rsqrtf(tk * (1.0f / HD) + EPSV);

    float wq = is_vid ? nq_vid[d] : nq_txt[d];
    float wk = is_vid ? nk_vid[d] : nk_txt[d];

    size_t o = ((size_t)(b * NH + h) * LSEQ + l) * HD + d;
    g_q[o] = __float2bfloat16(xq * rq * wq);
    g_k[o] = __float2bfloat16(xk * rk * wk);
    g_v[o] = __float2bfloat16(xv);
}

// =====================================================================
// Kernel 3: two-pass flash attention, exact reference softmax semantics:
//   pass1: m = rowmax(s*scale), l = sum exp(s*scale - m)   (online)
//   pass2: p = bf16( exp(s*scale - m) / l ),  O += p @ V
// One CTA = (b, h, 64 query rows). 256 threads. Dynamic smem 132 KB.
// =====================================================================
#define ATT_SMEM_FLOATS (8192 + 8192 + 8192 + 64*65 + 64*64 + 128)
#define ATT_SMEM_BYTES  (ATT_SMEM_FLOATS * 4)

__device__ __forceinline__ void load_tileT64x128(
    const __nv_bfloat16* __restrict__ g, float* __restrict__ dst, int tid)
{
    // dst[d][r] (stride 64), source row-major [64][128] bf16
    #pragma unroll
    for (int it = 0; it < 4; it++) {
        int idx = tid + it * 256;
        int r = idx >> 4, c8 = (idx & 15) << 3;
        uint4 u = *reinterpret_cast<const uint4*>(g + (size_t)r * HD + c8);
        dst[(c8 + 0) * 64 + r] = __uint_as_float(u.x << 16);
        dst[(c8 + 1) * 64 + r] = __uint_as_float(u.x & 0xffff0000u);
        dst[(c8 + 2) * 64 + r] = __uint_as_float(u.y << 16);
        dst[(c8 + 3) * 64 + r] = __uint_as_float(u.y & 0xffff0000u);
        dst[(c8 + 4) * 64 + r] = __uint_as_float(u.z << 16);
        dst[(c8 + 5) * 64 + r] = __uint_as_float(u.z & 0xffff0000u);
        dst[(c8 + 6) * 64 + r] = __uint_as_float(u.w << 16);
        dst[(c8 + 7) * 64 + r] = __uint_as_float(u.w & 0xffff0000u);
    }
}

__device__ __forceinline__ void load_tileV64x128(
    const __nv_bfloat16* __restrict__ g, float* __restrict__ dst, int tid)
{
    // dst[r][c] row-major fp32 [64][128]
    #pragma unroll
    for (int it = 0; it < 4; it++) {
        int idx = tid + it * 256;
        int r = idx >> 4, c8 = (idx & 15) << 3;
        uint4 u = *reinterpret_cast<const uint4*>(g + (size_t)r * HD + c8);
        float* p = dst + r * HD + c8;
        p[0] = __uint_as_float(u.x << 16); p[1] = __uint_as_float(u.x & 0xffff0000u);
        p[2] = __uint_as_float(u.y << 16); p[3] = __uint_as_float(u.y & 0xffff0000u);
        p[4] = __uint_as_float(u.z << 16); p[5] = __uint_as_float(u.z & 0xffff0000u);
        p[6] = __uint_as_float(u.w << 16); p[7] = __uint_as_float(u.w & 0xffff0000u);
    }
}

__device__ __forceinline__ void compute_S(
    const float* __restrict__ sQt, const float* __restrict__ sKt,
    float* __restrict__ sS, int tr, int tc)
{
    float s[4][4] = {};
    #pragma unroll 4
    for (int d = 0; d < HD; d++) {
        float4 av = *reinterpret_cast<const float4*>(&sQt[d * 64 + (tr << 2)]);
        float4 bw = *reinterpret_cast<const float4*>(&sKt[d * 64 + (tc << 2)]);
        float ar[4] = {av.x, av.y, av.z, av.w};
        float br[4] = {bw.x, bw.y, bw.z, bw.w};
        #pragma unroll
        for (int i = 0; i < 4; i++)
            #pragma unroll
            for (int j = 0; j < 4; j++)
                s[i][j] = fmaf(ar[i], br[j], s[i][j]);
    }
    #pragma unroll
    for (int i = 0; i < 4; i++)
        #pragma unroll
        for (int j = 0; j < 4; j++)
            sS[((tr << 2) + i) * 65 + (tc << 2) + j] = s[i][j];
}

__global__ void __launch_bounds__(256) attn_kernel()
{
    extern __shared__ __align__(16) float smem_f[];
    float* sQt = smem_f;                 // [128][64]
    float* sKt = sQt + 8192;             // [128][64]
    float* sV  = sKt + 8192;             // [64][128]
    float* sS  = sV + 8192;              // [64][65]
    float* sPt = sS + 64 * 65;           // [64(k)][64(r)]
    float* smx = sPt + 64 * 64;          // [64]
    float* slx = smx + 64;               // [64]

    const int qt = blockIdx.x;           // 0..31
    const int h  = blockIdx.y;           // 0..11
    const int b  = blockIdx.z;           // 0..1
    const int tid = threadIdx.x;
    const int tr = tid >> 4, tc = tid & 15;
    const float scale = 0.08838834764831845f;   // 1/sqrt(128)

    const size_t headbase = (size_t)(b * NH + h) * LSEQ * HD;
    const __nv_bfloat16* Qg = g_q + headbase + (size_t)qt * 64 * HD;
    const __nv_bfloat16* Kg = g_k + headbase;
    const __nv_bfloat16* Vg = g_v + headbase;

    load_tileT64x128(Qg, sQt, tid);
    if (tid < 64) { smx[tid] = -CUDART_INF_F; slx[tid] = 0.0f; }

    // ---------------- pass 1: exact row max + sumexp ----------------
    for (int kt = 0; kt < LSEQ / 64; kt++) {
        __syncthreads();
        load_tileT64x128(Kg + (size_t)kt * 64 * HD, sKt, tid);
        __syncthreads();
        compute_S(sQt, sKt, sS, tr, tc);
        __syncthreads();
        if (tid < 64) {
            const int r = tid;
            float mold = smx[r];
            float mx = mold;
            #pragma unroll 4
            for (int j = 0; j < 64; j++) mx = fmaxf(mx, sS[r * 65 + j] * scale);
            float acc = slx[r] * __expf(mold - mx);
            #pragma unroll 4
            for (int j = 0; j < 64; j++) acc += __expf(sS[r * 65 + j] * scale - mx);
            smx[r] = mx; slx[r] = acc;
        }
    }

    // ---------------- pass 2: normalized bf16 probs, P @ V ----------------
    float acc[4][8] = {};
    for (int kt = 0; kt < LSEQ / 64; kt++) {
        __syncthreads();
        load_tileT64x128(Kg + (size_t)kt * 64 * HD, sKt, tid);
        load_tileV64x128(Vg + (size_t)kt * 64 * HD, sV, tid);
        __syncthreads();
        compute_S(sQt, sKt, sS, tr, tc);
        __syncthreads();
        if (tid < 64) {
            const int r = tid;
            float mr = smx[r];
            float linv = 1.0f / slx[r];
            #pragma unroll 4
            for (int j = 0; j < 64; j++) {
                float p = __expf(sS[r * 65 + j] * scale - mr) * linv;
                sPt[j * 64 + r] = __bfloat162float(__float2bfloat16(p));
            }
        }
        __syncthreads();
        #pragma unroll 4
        for (int kk = 0; kk < 64; kk++) {
            float4 pv = *reinterpret_cast<const float4*>(&sPt[kk * 64 + (tr << 2)]);
            float4 v0 = *reinterpret_cast<const float4*>(&sV[kk * HD + (tc << 3)]);
            float4 v1 = *reinterpret_cast<const float4*>(&sV[kk * HD + (tc << 3) + 4]);
            float pr[4] = {pv.x, pv.y, pv.z, pv.w};
            float vr[8] = {v0.x, v0.y, v0.z, v0.w, v1.x, v1.y, v1.z, v1.w};
            #pragma unroll
            for (int i = 0; i < 4; i++)
                #pragma unroll
                for (int j = 0; j < 8; j++)
                    acc[i][j] = fmaf(pr[i], vr[j], acc[i][j]);
        }
    }

    // write attn output: g_attn[b*2048 + qt*64 + r][h*128 + c]
    #pragma unroll
    for (int i = 0; i < 4; i++) {
        size_t t = (size_t)b * LSEQ + qt * 64 + (tr << 2) + i;
        int c = h * HD + (tc << 3);
        float4 o0 = make_float4(acc[i][0], acc[i][1], acc[i][2], acc[i][3]);
        float4 o1 = make_float4(acc[i][4], acc[i][5], acc[i][6], acc[i][7]);
        *reinterpret_cast<float4*>(&g_attn[t * DIMIN + c])     = o0;
        *reinterpret_cast<float4*>(&g_attn[t * DIMIN + c + 4]) = o1;
    }
}

// =====================================================================
// Kernel 4: output projection  out = attn @ Wout_stream + bout
// writes vid_out rows then txt_out rows directly into d_out
// =====================================================================
__global__ void __launch_bounds__(256) gemm_out_kernel(
    const float* __restrict__ Wv, const float* __restrict__ bv,
    const float* __restrict__ Wt, const float* __restrict__ bt,
    float* __restrict__ out)
{
    __shared__ __align__(16) float As[16][64];
    __shared__ __align__(16) float Bs[16][64];

    const int row0 = blockIdx.y * 64;
    const int col0 = blockIdx.x * 64;
    const int b = row0 >> 11;
    const int l0 = row0 & 2047;

    const float* W; const float* bias; float* O;
    if (l0 < LV) { W = Wv; bias = bv; O = out + (size_t)(b * LV + l0) * DIMIN; }
    else         { W = Wt; bias = bt;
                   O = out + (size_t)BATCH * LV * DIMIN + (size_t)(b * LT + (l0 - LV)) * DIMIN; }
    const float* X = g_attn + (size_t)row0 * DIMIN;

    const int tid = threadIdx.x;
    const int tr = tid >> 4, tc = tid & 15;
    const int arow = tid >> 2,  ac4 = (tid & 3) << 2;
    const int brow = tid >> 4,  bc4 = (tid & 15) << 2;

    float acc[4][4] = {};

    for (int k0 = 0; k0 < DIMIN; k0 += 16) {
        float4 a = *reinterpret_cast<const float4*>(X + (size_t)arow * DIMIN + k0 + ac4);
        As[ac4 + 0][arow] = a.x; As[ac4 + 1][arow] = a.y;
        As[ac4 + 2][arow] = a.z; As[ac4 + 3][arow] = a.w;
        *reinterpret_cast<float4*>(&Bs[brow][bc4]) =
            *reinterpret_cast<const float4*>(W + (size_t)(k0 + brow) * DIMIN + col0 + bc4);
        __syncthreads();
        #pragma unroll
        for (int k = 0; k < 16; k++) {
            float4 av = *reinterpret_cast<const float4*>(&As[k][tr << 2]);
            float4 bw = *reinterpret_cast<const float4*>(&Bs[k][tc << 2]);
            float ar[4] = {av.x, av.y, av.z, av.w};
            float br[4] = {bw.x, bw.y, bw.z, bw.w};
            #pragma unroll
            for (int i = 0; i < 4; i++)
                #pragma unroll
                for (int j = 0; j < 4; j++)
                    acc[i][j] = fmaf(ar[i], br[j], acc[i][j]);
        }
        __syncthreads();
    }

    #pragma unroll
    for (int i = 0; i < 4; i++) {
        int rl = (tr << 2) + i;
        int c = col0 + (tc << 2);
        float4 bb = *reinterpret_cast<const float4*>(&bias[c]);
        float4 o = make_float4(acc[i][0] + bb.x, acc[i][1] + bb.y,
                               acc[i][2] + bb.z, acc[i][3] + bb.w);
        *reinterpret_cast<float4*>(&O[(size_t)rl * DIMIN + c]) = o;
    }
}

// =====================================================================
extern "C" void kernel_launch(void* const* d_in, const int* in_sizes, int n_in,
                              void* d_out, int out_size)
{
    const float* vid      = (const float*)d_in[0];
    const float* txt      = (const float*)d_in[1];
    const float* Wqkv_vid = (const float*)d_in[2];
    const float* bqkv_vid = (const float*)d_in[3];
    const float* Wqkv_txt = (const float*)d_in[4];
    const float* bqkv_txt = (const float*)d_in[5];
    const float* nq_vid   = (const float*)d_in[6];
    const float* nk_vid   = (const float*)d_in[7];
    const float* nq_txt   = (const float*)d_in[8];
    const float* nk_txt   = (const float*)d_in[9];
    const float* Wout_vid = (const float*)d_in[10];
    const float* bout_vid = (const float*)d_in[11];
    const float* Wout_txt = (const float*)d_in[12];
    const float* bout_txt = (const float*)d_in[13];
    float* out = (float*)d_out;

    // Stage 1: QKV projection
    gemm_qkv_kernel<<<dim3(QKVN / 64, NTOK / 64), 256>>>(
        vid, txt, Wqkv_vid, bqkv_vid, Wqkv_txt, bqkv_txt);

    // Stage 2: RMSNorm + bf16 pack
    norm_pack_kernel<<<dim3(NH, NTOK), 128>>>(nq_vid, nk_vid, nq_txt, nk_txt);

    // Stage 3: attention (132 KB dynamic smem)
    cudaFuncSetAttribute(attn_kernel, cudaFuncAttributeMaxDynamicSharedMemorySize,
                         ATT_SMEM_BYTES);
    attn_kernel<<<dim3(LSEQ / 64, NH, BATCH), 256, ATT_SMEM_BYTES>>>();

    // Stage 4: output projection (writes d_out: vid rows then txt rows)
    gemm_out_kernel<<<dim3(DIMIN / 64, NTOK / 64), 256>>>(
        Wout_vid, bout_vid, Wout_txt, bout_txt, out);
}

// round 15
// speedup vs baseline: 4.1725x; 4.1725x over previous
#include <cuda_runtime.h>
#include <cuda_bf16.h>
#include <cstdint>
#include <math_constants.h>

#define BATCH 2
#define LV 1920
#define LT 128
#define LSEQ 2048
#define NTOK 4096
#define NH 12
#define HD 128
#define DIMIN 1536
#define QKVN 4608
#define EPSV 1e-6f

// ---------------- scratch ----------------
__device__ float g_qkv[(size_t)NTOK * QKVN];
__device__ __nv_bfloat16 g_q[(size_t)BATCH * NH * LSEQ * HD];
__device__ __nv_bfloat16 g_k[(size_t)BATCH * NH * LSEQ * HD];
__device__ __nv_bfloat16 g_v[(size_t)BATCH * NH * LSEQ * HD];
__device__ float g_attn[(size_t)NTOK * DIMIN];

// ---------------- PTX helpers ----------------
__device__ __forceinline__ uint32_t sm_addr(const void* p) {
    return (uint32_t)__cvta_generic_to_shared(p);
}
__device__ __forceinline__ uint32_t f2tf32(float x) {
    uint32_t r; asm("cvt.rna.tf32.f32 %0, %1;" : "=r"(r) : "f"(x)); return r;
}
// 3xTF32 split: x = hi + lo (hi/lo are tf32 values in fp32 bit layout)
__device__ __forceinline__ void split_tf32(float x, uint32_t& hi, uint32_t& lo) {
    hi = f2tf32(x);
    lo = f2tf32(x - __uint_as_float(hi));
}
__device__ __forceinline__ uint32_t pack_bf16x2(float lo, float hi) {
    uint32_t d; asm("cvt.rn.bf16x2.f32 %0, %1, %2;" : "=r"(d) : "f"(hi), "f"(lo)); return d;
}
__device__ __forceinline__ void ldsm4(uint32_t& r0, uint32_t& r1, uint32_t& r2, uint32_t& r3, uint32_t a) {
    asm volatile("ldmatrix.sync.aligned.m8n8.x4.shared.b16 {%0,%1,%2,%3},[%4];"
                 : "=r"(r0), "=r"(r1), "=r"(r2), "=r"(r3) : "r"(a));
}
__device__ __forceinline__ void ldsm4t(uint32_t& r0, uint32_t& r1, uint32_t& r2, uint32_t& r3, uint32_t a) {
    asm volatile("ldmatrix.sync.aligned.m8n8.x4.trans.shared.b16 {%0,%1,%2,%3},[%4];"
                 : "=r"(r0), "=r"(r1), "=r"(r2), "=r"(r3) : "r"(a));
}
__device__ __forceinline__ void mma_bf16(float* c, const uint32_t* a, uint32_t b0, uint32_t b1) {
    asm volatile("mma.sync.aligned.m16n8k16.row.col.f32.bf16.bf16.f32 "
                 "{%0,%1,%2,%3},{%4,%5,%6,%7},{%8,%9},{%0,%1,%2,%3};"
                 : "+f"(c[0]), "+f"(c[1]), "+f"(c[2]), "+f"(c[3])
                 : "r"(a[0]), "r"(a[1]), "r"(a[2]), "r"(a[3]), "r"(b0), "r"(b1));
}
__device__ __forceinline__ void mma_tf32(float* c, const uint32_t* a, uint32_t b0, uint32_t b1) {
    asm volatile("mma.sync.aligned.m16n8k8.row.col.f32.tf32.tf32.f32 "
                 "{%0,%1,%2,%3},{%4,%5,%6,%7},{%8,%9},{%0,%1,%2,%3};"
                 : "+f"(c[0]), "+f"(c[1]), "+f"(c[2]), "+f"(c[3])
                 : "r"(a[0]), "r"(a[1]), "r"(a[2]), "r"(a[3]), "r"(b0), "r"(b1));
}
__device__ __forceinline__ void cp16(uint32_t dst, const void* src) {
    asm volatile("cp.async.cg.shared.global [%0],[%1],16;" :: "r"(dst), "l"(src) : "memory");
}
#define CP_COMMIT() asm volatile("cp.async.commit_group;" ::: "memory")
#define CP_WAIT0()  asm volatile("cp.async.wait_group 0;" ::: "memory")
#define CP_WAIT1()  asm volatile("cp.async.wait_group 1;" ::: "memory")

// =====================================================================
// 3xTF32 GEMM core: BM=128, BN=128, BK=32, 256 threads (8 warps 2x4)
// acc += hi*hi + lo*hi + hi*lo   (~fp32-equivalent precision)
// =====================================================================
#define GEMM_SMEM_BYTES ((2 * 128 * 36 + 2 * 32 * 128) * 4)

struct GemmFrag { float acc[4][4][4]; };

__device__ __forceinline__ void gemm_load_tile(
    float* As, float* Bs, const float* X, const float* W, int N, int k0, int col0, int tid)
{
    #pragma unroll
    for (int i = 0; i < 4; i++) {
        int idx = tid + i * 256;
        int ar = idx >> 3, ac4 = (idx & 7) << 2;
        cp16(sm_addr(&As[ar * 36 + ac4]), X + (size_t)ar * DIMIN + k0 + ac4);
    }
    #pragma unroll
    for (int i = 0; i < 4; i++) {
        int idx = tid + i * 256;
        int br = idx >> 5, bc4 = (idx & 31) << 2;
        cp16(sm_addr(&Bs[br * 128 + (bc4 ^ ((br & 3) << 3))]),
             W + (size_t)(k0 + br) * N + col0 + bc4);
    }
}

__device__ __forceinline__ void gemm_compute_tile(
    const float* As, const float* Bs, GemmFrag& F, int wr, int wc, int g, int t4)
{
    #pragma unroll
    for (int ks = 0; ks < 4; ks++) {
        const int kk = ks * 8 + t4;
        uint32_t ah[4][4], al[4][4], bh[4][2], bl[4][2];
        #pragma unroll
        for (int mi = 0; mi < 4; mi++) {
            const float* Ab = As + (wr * 64 + mi * 16 + g) * 36;
            split_tf32(Ab[kk],              ah[mi][0], al[mi][0]);
            split_tf32(Ab[8 * 36 + kk],     ah[mi][1], al[mi][1]);
            split_tf32(Ab[kk + 4],          ah[mi][2], al[mi][2]);
            split_tf32(Ab[8 * 36 + kk + 4], ah[mi][3], al[mi][3]);
        }
        #pragma unroll
        for (int ni = 0; ni < 4; ni++) {
            int col = (wc * 32 + ni * 8 + g) ^ (t4 << 3);
            split_tf32(Bs[kk * 128 + col],       bh[ni][0], bl[ni][0]);
            split_tf32(Bs[(kk + 4) * 128 + col], bh[ni][1], bl[ni][1]);
        }
        #pragma unroll
        for (int mi = 0; mi < 4; mi++)
            #pragma unroll
            for (int ni = 0; ni < 4; ni++) {
                mma_tf32(F.acc[mi][ni], ah[mi], bh[ni][0], bh[ni][1]);
                mma_tf32(F.acc[mi][ni], al[mi], bh[ni][0], bh[ni][1]);
                mma_tf32(F.acc[mi][ni], ah[mi], bl[ni][0], bl[ni][1]);
            }
    }
}

// ---------------- QKV projection ----------------
__global__ void __launch_bounds__(256) gemm_qkv_kernel(
    const float* __restrict__ vid, const float* __restrict__ txt,
    const float* __restrict__ Wv, const float* __restrict__ bv,
    const float* __restrict__ Wt, const float* __restrict__ bt)
{
    extern __shared__ __align__(16) float smem[];
    float* As = smem;                 // [2][128][36]
    float* Bs = smem + 2 * 128 * 36;  // [2][32][128]

    const int row0 = blockIdx.y * 128;
    const int col0 = blockIdx.x * 128;
    const int b = row0 >> 11;
    const int l0 = row0 & 2047;

    const float* X; const float* W; const float* bias;
    if (l0 < LV) { X = vid + (size_t)(b * LV + l0) * DIMIN;        W = Wv; bias = bv; }
    else         { X = txt + (size_t)(b * LT + (l0 - LV)) * DIMIN; W = Wt; bias = bt; }

    const int tid = threadIdx.x;
    const int wid = tid >> 5, lane = tid & 31;
    const int wr = wid >> 2, wc = wid & 3;
    const int g = lane >> 2, t4 = lane & 3;

    GemmFrag F;
    #pragma unroll
    for (int mi = 0; mi < 4; mi++)
        #pragma unroll
        for (int ni = 0; ni < 4; ni++)
            #pragma unroll
            for (int q = 0; q < 4; q++) F.acc[mi][ni][q] = 0.0f;

    const int NKT = DIMIN / 32;
    int buf = 0;
    gemm_load_tile(As, Bs, X, W, QKVN, 0, col0, tid);
    CP_COMMIT();

    for (int t = 0; t < NKT; t++) {
        if (t + 1 < NKT) {
            gemm_load_tile(As + (buf ^ 1) * 128 * 36, Bs + (buf ^ 1) * 32 * 128,
                           X, W, QKVN, (t + 1) * 32, col0, tid);
            CP_COMMIT();
            CP_WAIT1();
        } else {
            CP_WAIT0();
        }
        __syncthreads();
        gemm_compute_tile(As + buf * 128 * 36, Bs + buf * 32 * 128, F, wr, wc, g, t4);
        __syncthreads();
        buf ^= 1;
    }

    #pragma unroll
    for (int mi = 0; mi < 4; mi++) {
        #pragma unroll
        for (int ni = 0; ni < 4; ni++) {
            int gr = row0 + wr * 64 + mi * 16 + g;
            int gc = col0 + wc * 32 + ni * 8 + 2 * t4;
            float2 bb = *reinterpret_cast<const float2*>(&bias[gc]);
            float2 o0 = make_float2(F.acc[mi][ni][0] + bb.x, F.acc[mi][ni][1] + bb.y);
            float2 o1 = make_float2(F.acc[mi][ni][2] + bb.x, F.acc[mi][ni][3] + bb.y);
            *reinterpret_cast<float2*>(&g_qkv[(size_t)gr * QKVN + gc]) = o0;
            *reinterpret_cast<float2*>(&g_qkv[(size_t)(gr + 8) * QKVN + gc]) = o1;
        }
    }
}

// ---------------- output projection ----------------
__global__ void __launch_bounds__(256) gemm_out_kernel(
    const float* __restrict__ Wv, const float* __restrict__ bv,
    const float* __restrict__ Wt, const float* __restrict__ bt,
    float* __restrict__ out)
{
    extern __shared__ __align__(16) float smem[];
    float* As = smem;
    float* Bs = smem + 2 * 128 * 36;

    const int row0 = blockIdx.y * 128;
    const int col0 = blockIdx.x * 128;
    const int b = row0 >> 11;
    const int l0 = row0 & 2047;

    const float* W; const float* bias; float* O;
    if (l0 < LV) { W = Wv; bias = bv; O = out + (size_t)(b * LV + l0) * DIMIN; }
    else         { W = Wt; bias = bt;
                   O = out + (size_t)BATCH * LV * DIMIN + (size_t)(b * LT + (l0 - LV)) * DIMIN; }
    const float* X = g_attn + (size_t)row0 * DIMIN;

    const int tid = threadIdx.x;
    const int wid = tid >> 5, lane = tid & 31;
    const int wr = wid >> 2, wc = wid & 3;
    const int g = lane >> 2, t4 = lane & 3;

    GemmFrag F;
    #pragma unroll
    for (int mi = 0; mi < 4; mi++)
        #pragma unroll
        for (int ni = 0; ni < 4; ni++)
            #pragma unroll
            for (int q = 0; q < 4; q++) F.acc[mi][ni][q] = 0.0f;

    const int NKT = DIMIN / 32;
    int buf = 0;
    gemm_load_tile(As, Bs, X, W, DIMIN, 0, col0, tid);
    CP_COMMIT();

    for (int t = 0; t < NKT; t++) {
        if (t + 1 < NKT) {
            gemm_load_tile(As + (buf ^ 1) * 128 * 36, Bs + (buf ^ 1) * 32 * 128,
                           X, W, DIMIN, (t + 1) * 32, col0, tid);
            CP_COMMIT();
            CP_WAIT1();
        } else {
            CP_WAIT0();
        }
        __syncthreads();
        gemm_compute_tile(As + buf * 128 * 36, Bs + buf * 32 * 128, F, wr, wc, g, t4);
        __syncthreads();
        buf ^= 1;
    }

    #pragma unroll
    for (int mi = 0; mi < 4; mi++) {
        #pragma unroll
        for (int ni = 0; ni < 4; ni++) {
            int lr = wr * 64 + mi * 16 + g;
            int gc = col0 + wc * 32 + ni * 8 + 2 * t4;
            float2 bb = *reinterpret_cast<const float2*>(&bias[gc]);
            float2 o0 = make_float2(F.acc[mi][ni][0] + bb.x, F.acc[mi][ni][1] + bb.y);
            float2 o1 = make_float2(F.acc[mi][ni][2] + bb.x, F.acc[mi][ni][3] + bb.y);
            *reinterpret_cast<float2*>(&O[(size_t)lr * DIMIN + gc]) = o0;
            *reinterpret_cast<float2*>(&O[(size_t)(lr + 8) * DIMIN + gc]) = o1;
        }
    }
}

// =====================================================================
// RMSNorm + bf16 pack
// =====================================================================
__global__ void __launch_bounds__(128) norm_pack_kernel(
    const float* __restrict__ nq_vid, const float* __restrict__ nk_vid,
    const float* __restrict__ nq_txt, const float* __restrict__ nk_txt)
{
    const int h = blockIdx.x;
    const int t = blockIdx.y;
    const int d = threadIdx.x;
    const int b = t >> 11, l = t & 2047;
    const bool is_vid = (l < LV);

    const float* base = g_qkv + (size_t)t * QKVN + h * HD;
    float xq = base[d];
    float xk = base[DIMIN + d];
    float xv = base[2 * DIMIN + d];

    float sq = xq * xq, sk = xk * xk;
    #pragma unroll
    for (int o = 16; o; o >>= 1) {
        sq += __shfl_down_sync(0xffffffffu, sq, o);
        sk += __shfl_down_sync(0xffffffffu, sk, o);
    }
    __shared__ float shq[4], shk[4];
    const int wid = d >> 5, lane = d & 31;
    if (lane == 0) { shq[wid] = sq; shk[wid] = sk; }
    __syncthreads();
    float tq = shq[0] + shq[1] + shq[2] + shq[3];
    float tk = shk[0] + shk[1] + shk[2] + shk[3];
    float rq = rsqrtf(tq * (1.0f / HD) + EPSV);
    float rk = rsqrtf(tk * (1.0f / HD) + EPSV);

    float wq = is_vid ? nq_vid[d] : nq_txt[d];
    float wk = is_vid ? nk_vid[d] : nk_txt[d];

    size_t o = ((size_t)(b * NH + h) * LSEQ + l) * HD + d;
    g_q[o] = __float2bfloat16(xq * rq * wq);
    g_k[o] = __float2bfloat16(xk * rk * wk);
    g_v[o] = __float2bfloat16(xv);
}

// =====================================================================
// Attention: bf16 mma, two-pass exact softmax with bf16 probs.
// CTA = 64 q-rows x one (b,h). 128 threads (4 warps, 16 q-rows each).
// smem: sQ/sK/sV [64][136] bf16
// =====================================================================
#define APAD 136
#define ATT_SMEM_BYTES (3 * 64 * APAD * 2)

__device__ __forceinline__ void att_load_tile(__nv_bfloat16* dst,
                                              const __nv_bfloat16* src, int tid)
{
    // 64 rows x 128 cols bf16 = 1024 16B-chunks = 8 iters of 128 threads
    #pragma unroll
    for (int i = 0; i < 8; i++) {
        int idx = tid + i * 128;
        int r = idx >> 4, c8 = (idx & 15) << 3;
        cp16(sm_addr(&dst[r * APAD + c8]), src + (size_t)r * HD + c8);
    }
}

__global__ void __launch_bounds__(128) attn_mma_kernel()
{
    extern __shared__ __align__(16) char smem_raw[];
    __nv_bfloat16* sQ = reinterpret_cast<__nv_bfloat16*>(smem_raw);
    __nv_bfloat16* sK = sQ + 64 * APAD;
    __nv_bfloat16* sV = sK + 64 * APAD;

    const int qt = blockIdx.x, h = blockIdx.y, b = blockIdx.z;
    const int tid = threadIdx.x, wid = tid >> 5, lane = tid & 31;
    const int g = lane >> 2, t4 = lane & 3;
    const float scale = 0.08838834764831845f;

    const size_t headbase = (size_t)(b * NH + h) * LSEQ * HD;
    const __nv_bfloat16* Qg = g_q + headbase + (size_t)qt * 64 * HD;
    const __nv_bfloat16* Kg = g_k + headbase;
    const __nv_bfloat16* Vg = g_v + headbase;

    att_load_tile(sQ, Qg, tid);
    CP_COMMIT(); CP_WAIT0();
    __syncthreads();

    // preload Q A-frags: 8 k16-blocks
    uint32_t qa[8][4];
    {
        int row = wid * 16 + (lane & 15);
        int coff = (lane >> 4) << 3;
        #pragma unroll
        for (int kb = 0; kb < 8; kb++)
            ldsm4(qa[kb][0], qa[kb][1], qa[kb][2], qa[kb][3],
                  sm_addr(&sQ[row * APAD + kb * 16 + coff]));
    }

    float m0r = -CUDART_INF_F, m1r = -CUDART_INF_F, l0r = 0.0f, l1r = 0.0f;

    const int k_row = (lane & 7) + ((lane >> 4) << 3);
    const int k_coff = ((lane >> 3) & 1) << 3;
    const int v_row = (lane & 7) + (((lane >> 3) & 1) << 3);
    const int v_coff = (lane >> 4) << 3;

    // ---------------- pass 1 ----------------
    for (int kt = 0; kt < LSEQ / 64; kt++) {
        __syncthreads();
        att_load_tile(sK, Kg + (size_t)kt * 64 * HD, tid);
        CP_COMMIT(); CP_WAIT0();
        __syncthreads();

        float s[8][4];
        #pragma unroll
        for (int j = 0; j < 8; j++)
            #pragma unroll
            for (int q = 0; q < 4; q++) s[j][q] = 0.0f;

        #pragma unroll
        for (int kb = 0; kb < 8; kb++) {
            #pragma unroll
            for (int nn = 0; nn < 4; nn++) {
                uint32_t b0, b1, b2, b3;
                ldsm4(b0, b1, b2, b3,
                      sm_addr(&sK[(nn * 16 + k_row) * APAD + kb * 16 + k_coff]));
                mma_bf16(s[2 * nn],     qa[kb], b0, b1);
                mma_bf16(s[2 * nn + 1], qa[kb], b2, b3);
            }
        }

        float mt0 = -CUDART_INF_F, mt1 = -CUDART_INF_F;
        #pragma unroll
        for (int j = 0; j < 8; j++) {
            mt0 = fmaxf(mt0, fmaxf(s[j][0], s[j][1]));
            mt1 = fmaxf(mt1, fmaxf(s[j][2], s[j][3]));
        }
        mt0 = fmaxf(mt0, __shfl_xor_sync(0xffffffffu, mt0, 1));
        mt0 = fmaxf(mt0, __shfl_xor_sync(0xffffffffu, mt0, 2));
        mt1 = fmaxf(mt1, __shfl_xor_sync(0xffffffffu, mt1, 1));
        mt1 = fmaxf(mt1, __shfl_xor_sync(0xffffffffu, mt1, 2));
        float mn0 = fmaxf(m0r, mt0 * scale);
        float mn1 = fmaxf(m1r, mt1 * scale);
        float sum0 = 0.0f, sum1 = 0.0f;
        #pragma unroll
        for (int j = 0; j < 8; j++) {
            sum0 += __expf(s[j][0] * scale - mn0) + __expf(s[j][1] * scale - mn0);
            sum1 += __expf(s[j][2] * scale - mn1) + __expf(s[j][3] * scale - mn1);
        }
        sum0 += __shfl_xor_sync(0xffffffffu, sum0, 1);
        sum0 += __shfl_xor_sync(0xffffffffu, sum0, 2);
        sum1 += __shfl_xor_sync(0xffffffffu, sum1, 1);
        sum1 += __shfl_xor_sync(0xffffffffu, sum1, 2);
        l0r = l0r * __expf(m0r - mn0) + sum0;  m0r = mn0;
        l1r = l1r * __expf(m1r - mn1) + sum1;  m1r = mn1;
    }

    const float linv0 = 1.0f / l0r;
    const float linv1 = 1.0f / l1r;

    // ---------------- pass 2 ----------------
    float oacc[16][4];
    #pragma unroll
    for (int j = 0; j < 16; j++)
        #pragma unroll
        for (int q = 0; q < 4; q++) oacc[j][q] = 0.0f;

    for (int kt = 0; kt < LSEQ / 64; kt++) {
        __syncthreads();
        att_load_tile(sK, Kg + (size_t)kt * 64 * HD, tid);
        att_load_tile(sV, Vg + (size_t)kt * 64 * HD, tid);
        CP_COMMIT(); CP_WAIT0();
        __syncthreads();

        float s[8][4];
        #pragma unroll
        for (int j = 0; j < 8; j++)
            #pragma unroll
            for (int q = 0; q < 4; q++) s[j][q] = 0.0f;

        #pragma unroll
        for (int kb = 0; kb < 8; kb++) {
            #pragma unroll
            for (int nn = 0; nn < 4; nn++) {
                uint32_t b0, b1, b2, b3;
                ldsm4(b0, b1, b2, b3,
                      sm_addr(&sK[(nn * 16 + k_row) * APAD + kb * 16 + k_coff]));
                mma_bf16(s[2 * nn],     qa[kb], b0, b1);
                mma_bf16(s[2 * nn + 1], qa[kb], b2, b3);
            }
        }

        // probs -> bf16 A-frags (reference rounding: normalized then bf16)
        uint32_t pa[4][4];
        #pragma unroll
        for (int j = 0; j < 8; j++) {
            float p0 = __expf(s[j][0] * scale - m0r) * linv0;
            float p1 = __expf(s[j][1] * scale - m0r) * linv0;
            float p2 = __expf(s[j][2] * scale - m1r) * linv1;
            float p3 = __expf(s[j][3] * scale - m1r) * linv1;
            int kb = j >> 1, half = j & 1;
            pa[kb][2 * half + 0] = pack_bf16x2(p0, p1);
            pa[kb][2 * half + 1] = pack_bf16x2(p2, p3);
        }

        #pragma unroll
        for (int kb = 0; kb < 4; kb++) {
            #pragma unroll
            for (int nn = 0; nn < 8; nn++) {
                uint32_t v0, v1, v2, v3;
                ldsm4t(v0, v1, v2, v3,
                       sm_addr(&sV[(kb * 16 + v_row) * APAD + nn * 16 + v_coff]));
                mma_bf16(oacc[2 * nn],     pa[kb], v0, v1);
                mma_bf16(oacc[2 * nn + 1], pa[kb], v2, v3);
            }
        }
    }

    const size_t trow0 = (size_t)b * LSEQ + qt * 64 + wid * 16;
    #pragma unroll
    for (int j = 0; j < 16; j++) {
        int c = h * HD + j * 8 + 2 * t4;
        float2 o0 = make_float2(oacc[j][0], oacc[j][1]);
        float2 o1 = make_float2(oacc[j][2], oacc[j][3]);
        *reinterpret_cast<float2*>(&g_attn[(trow0 + g) * DIMIN + c]) = o0;
        *reinterpret_cast<float2*>(&g_attn[(trow0 + g + 8) * DIMIN + c]) = o1;
    }
}

// =====================================================================
extern "C" void kernel_launch(void* const* d_in, const int* in_sizes, int n_in,
                              void* d_out, int out_size)
{
    const float* vid      = (const float*)d_in[0];
    const float* txt      = (const float*)d_in[1];
    const float* Wqkv_vid = (const float*)d_in[2];
    const float* bqkv_vid = (const float*)d_in[3];
    const float* Wqkv_txt = (const float*)d_in[4];
    const float* bqkv_txt = (const float*)d_in[5];
    const float* nq_vid   = (const float*)d_in[6];
    const float* nk_vid   = (const float*)d_in[7];
    const float* nq_txt   = (const float*)d_in[8];
    const float* nk_txt   = (const float*)d_in[9];
    const float* Wout_vid = (const float*)d_in[10];
    const float* bout_vid = (const float*)d_in[11];
    const float* Wout_txt = (const float*)d_in[12];
    const float* bout_txt = (const float*)d_in[13];
    float* out = (float*)d_out;

    cudaFuncSetAttribute(gemm_qkv_kernel, cudaFuncAttributeMaxDynamicSharedMemorySize, GEMM_SMEM_BYTES);
    cudaFuncSetAttribute(gemm_out_kernel, cudaFuncAttributeMaxDynamicSharedMemorySize, GEMM_SMEM_BYTES);
    cudaFuncSetAttribute(attn_mma_kernel, cudaFuncAttributeMaxDynamicSharedMemorySize, ATT_SMEM_BYTES);

    gemm_qkv_kernel<<<dim3(QKVN / 128, NTOK / 128), 256, GEMM_SMEM_BYTES>>>(
        vid, txt, Wqkv_vid, bqkv_vid, Wqkv_txt, bqkv_txt);

    norm_pack_kernel<<<dim3(NH, NTOK), 128>>>(nq_vid, nk_vid, nq_txt, nk_txt);

    attn_mma_kernel<<<dim3(LSEQ / 64, NH, BATCH), 128, ATT_SMEM_BYTES>>>();

    gemm_out_kernel<<<dim3(DIMIN / 128, NTOK / 128), 256, GEMM_SMEM_BYTES>>>(
        Wout_vid, bout_vid, Wout_txt, bout_txt, out);
}